// round 2
// baseline (speedup 1.0000x reference)
#include <cuda_runtime.h>
#include <cstdint>

// Problem constants (fixed by the dataset)
#define Bsz 8
#define Nn  512
#define Dd  256
#define Ee  16384

// Scratch: AB[b*N + n][0:256] = F@W1_top, [256:512] = F@W1_bot  (8 MB)
__device__ float g_AB[(size_t)Bsz * Nn * 512];
// Edge-index dtype flag: 1 if stored as int64, 0 if int32
__device__ int g_edge_is64;

// ---------------------------------------------------------------------------
// Detect edge_index storage width. Values are in [0, 512), so if the buffer
// is int64, every high 32-bit word is zero. Check 32 odd-position words.
// ---------------------------------------------------------------------------
__global__ void detect_kernel(const int* __restrict__ edge32)
{
    const int lane = threadIdx.x;          // 32 threads
    int v = edge32[2 * lane + 1];          // odd words
    unsigned any = __ballot_sync(0xffffffffu, v != 0);
    if (lane == 0) g_edge_is64 = (any == 0u) ? 1 : 0;
}

// ---------------------------------------------------------------------------
// Phase 1: SGEMM  AB(4096 x 512) = F(4096 x 256) @ Wc(256 x 512)
//   Wc[k][j] = W1[k*256 + j]             for j < 256   (W1_top)
//            = W1[(256+k)*256 + (j-256)] for j >= 256  (W1_bot)
// Tiling: BM=64, BN=64, BK=16, 256 threads, 4x4 microtile.
// ---------------------------------------------------------------------------
#define BM 64
#define BN 64
#define BK 16

__global__ __launch_bounds__(256) void gemm_kernel(
    const float* __restrict__ F, const float* __restrict__ W1,
    float* __restrict__ AB)
{
    __shared__ float Fs[BK][BM];
    __shared__ float Ws[BK][BN];

    const int tid = threadIdx.x;
    const int m0 = blockIdx.y * BM;
    const int n0 = blockIdx.x * BN;

    // n-tile lies entirely within one half (n0 multiple of 64)
    const float* Wsrc = (n0 < 256) ? (W1 + n0) : (W1 + 256 * 256 + (n0 - 256));

    const int ty = tid >> 4;          // 0..15 (m group)
    const int tx = tid & 15;          // 0..15 (n group)

    const int lrow = tid >> 2;        // 0..63  F row within tile
    const int lcol = (tid & 3) * 4;   // 0,4,8,12 (k within tile)
    const int wrow = tid >> 4;        // 0..15  k within tile
    const int wcol = (tid & 15) * 4;  // n within tile

    float c[4][4] = {};

    for (int k0 = 0; k0 < 256; k0 += BK) {
        float4 fv = *(const float4*)(F + (size_t)(m0 + lrow) * 256 + k0 + lcol);
        Fs[lcol + 0][lrow] = fv.x;
        Fs[lcol + 1][lrow] = fv.y;
        Fs[lcol + 2][lrow] = fv.z;
        Fs[lcol + 3][lrow] = fv.w;

        *(float4*)&Ws[wrow][wcol] =
            *(const float4*)(Wsrc + (size_t)(k0 + wrow) * 256 + wcol);

        __syncthreads();

#pragma unroll
        for (int kk = 0; kk < BK; kk++) {
            float4 a  = *(const float4*)&Fs[kk][ty * 4];
            float4 bv = *(const float4*)&Ws[kk][tx * 4];
            c[0][0] += a.x * bv.x; c[0][1] += a.x * bv.y; c[0][2] += a.x * bv.z; c[0][3] += a.x * bv.w;
            c[1][0] += a.y * bv.x; c[1][1] += a.y * bv.y; c[1][2] += a.y * bv.z; c[1][3] += a.y * bv.w;
            c[2][0] += a.z * bv.x; c[2][1] += a.z * bv.y; c[2][2] += a.z * bv.z; c[2][3] += a.z * bv.w;
            c[3][0] += a.w * bv.x; c[3][1] += a.w * bv.y; c[3][2] += a.w * bv.z; c[3][3] += a.w * bv.w;
        }
        __syncthreads();
    }

#pragma unroll
    for (int i = 0; i < 4; i++) {
        float4 v = make_float4(c[i][0], c[i][1], c[i][2], c[i][3]);
        *(float4*)(AB + (size_t)(m0 + ty * 4 + i) * 512 + n0 + tx * 4) = v;
    }
}

// ---------------------------------------------------------------------------
// Phase 2: per-(b,e) edge MLP tail + scatter.
// One warp per (b,e), 4 pairs per warp sequentially. b1/W2 frags in registers.
// Reads hit L2 (AB is 8 MB, edge-gathered).
// ---------------------------------------------------------------------------
__global__ __launch_bounds__(256) void edge_kernel(
    const float* __restrict__ AB,
    const float* __restrict__ b1,
    const float* __restrict__ W2,
    const float* __restrict__ b2,
    const void* __restrict__ edge_raw,
    float* __restrict__ out)
{
    const int tid  = threadIdx.x;
    const int warp = tid >> 5;
    const int lane = tid & 31;
    const int base = lane * 4;

    const int is64 = g_edge_is64;
    const int*       e32 = (const int*)edge_raw;
    const long long* e64 = (const long long*)edge_raw;

    const float4 b1a = *(const float4*)(b1 + base);
    const float4 b1b = *(const float4*)(b1 + base + 128);
    const float4 w2a = *(const float4*)(W2 + base);
    const float4 w2b = *(const float4*)(W2 + base + 128);
    const float  b2v = b2[0];

    const int wslot = blockIdx.x * 8 + warp;  // 0..32767

#pragma unroll
    for (int r = 0; r < 4; r++) {
        const int g = wslot * 4 + r;            // 0..131071  (b,e) pair
        const int b = g >> 14;                  // E = 16384
        const int e = g & (Ee - 1);

        int src, dst;
        if (is64) {
            src = (int)e64[e];
            dst = (int)e64[Ee + e];
        } else {
            src = e32[e];
            dst = e32[Ee + e];
        }

        const float* ar = AB + (((size_t)b * Nn + src) << 9);
        const float* br = AB + (((size_t)b * Nn + dst) << 9) + 256;

        float4 a0 = *(const float4*)(ar + base);
        float4 a1 = *(const float4*)(ar + base + 128);
        float4 c0 = *(const float4*)(br + base);
        float4 c1 = *(const float4*)(br + base + 128);

        float acc;
        acc  = fmaxf(a0.x + c0.x + b1a.x, 0.f) * w2a.x;
        acc += fmaxf(a0.y + c0.y + b1a.y, 0.f) * w2a.y;
        acc += fmaxf(a0.z + c0.z + b1a.z, 0.f) * w2a.z;
        acc += fmaxf(a0.w + c0.w + b1a.w, 0.f) * w2a.w;
        acc += fmaxf(a1.x + c1.x + b1b.x, 0.f) * w2b.x;
        acc += fmaxf(a1.y + c1.y + b1b.y, 0.f) * w2b.y;
        acc += fmaxf(a1.z + c1.z + b1b.z, 0.f) * w2b.z;
        acc += fmaxf(a1.w + c1.w + b1b.w, 0.f) * w2b.w;

        acc += __shfl_xor_sync(0xffffffffu, acc, 16);
        acc += __shfl_xor_sync(0xffffffffu, acc, 8);
        acc += __shfl_xor_sync(0xffffffffu, acc, 4);
        acc += __shfl_xor_sync(0xffffffffu, acc, 2);
        acc += __shfl_xor_sync(0xffffffffu, acc, 1);

        if (lane == 0) {
            const float z = acc + b2v;
            const float s = 1.0f / (1.0f + expf(-z));
            out[((size_t)b << 18) + ((size_t)src << 9) + (size_t)dst] = s;
        }
    }
}

// ---------------------------------------------------------------------------
extern "C" void kernel_launch(void* const* d_in, const int* in_sizes, int n_in,
                              void* d_out, int out_size)
{
    const float* features = (const float*)d_in[0];   // (8,512,256)
    const float* W1       = (const float*)d_in[1];   // (512,256)
    const float* b1       = (const float*)d_in[2];   // (256)
    const float* W2       = (const float*)d_in[3];   // (256,1)
    const float* b2       = (const float*)d_in[4];   // (1)
    const void*  edge     = d_in[5];                 // (2,16384) int32 or int64
    float*       out      = (float*)d_out;           // (8,512,512)

    float* AB;
    cudaGetSymbolAddress((void**)&AB, g_AB);

    // Detect edge dtype (tiny, once per launch — deterministic)
    detect_kernel<<<1, 32>>>((const int*)edge);

    // Zero output (scatter only writes edge slots)
    cudaMemsetAsync(d_out, 0, (size_t)out_size * sizeof(float));

    // Phase 1: AB = F @ Wc
    dim3 ggrid(512 / BN, (Bsz * Nn) / BM);  // (8, 64)
    gemm_kernel<<<ggrid, 256>>>(features, W1, AB);

    // Phase 2: edge MLP tail + scatter. 131072 (b,e) / (8 warps * 4) = 4096 blocks
    edge_kernel<<<4096, 256>>>(AB, b1, W2, b2, edge, out);
}

// round 3
// speedup vs baseline: 1.0293x; 1.0293x over previous
#include <cuda_runtime.h>
#include <cstdint>

// Problem constants (fixed by the dataset)
#define Bsz 8
#define Nn  512
#define Dd  256
#define Ee  16384

// Scratch: AB[b*N + n][0:256] = F@W1_top, [256:512] = F@W1_bot  (8 MB)
__device__ float g_AB[(size_t)Bsz * Nn * 512];

// ---------------------------------------------------------------------------
// Packed f32x2 helpers (Blackwell FFMA2 — only reachable via PTX)
// ---------------------------------------------------------------------------
__device__ __forceinline__ unsigned long long pack_dup(float x) {
    unsigned long long r;
    asm("mov.b64 %0, {%1, %1};" : "=l"(r) : "f"(x));
    return r;
}
__device__ __forceinline__ void ffma2(unsigned long long& c,
                                      unsigned long long a,
                                      unsigned long long b) {
    asm("fma.rn.f32x2 %0, %1, %2, %0;" : "+l"(c) : "l"(a), "l"(b));
}
__device__ __forceinline__ float2 unpack2(unsigned long long v) {
    float2 f;
    asm("mov.b64 {%0, %1}, %2;" : "=f"(f.x), "=f"(f.y) : "l"(v));
    return f;
}

// ---------------------------------------------------------------------------
// Phase 1: SGEMM  AB(4096 x 512) = F(4096 x 256) @ Wc(256 x 512)
//   Wc[k][j] = W1[k*256 + j]             for j < 256   (W1_top)
//            = W1[(256+k)*256 + (j-256)] for j >= 256  (W1_bot)
// Tiling: BM=64, BN=64, BK=16, 256 threads, 4x4 microtile, FFMA2 inner loop.
// ---------------------------------------------------------------------------
#define BM 64
#define BN 64
#define BK 16

__global__ __launch_bounds__(256) void gemm_kernel(
    const float* __restrict__ F, const float* __restrict__ W1,
    float* __restrict__ AB)
{
    __shared__ float Fs[BK][BM];
    __shared__ float Ws[BK][BN];

    const int tid = threadIdx.x;
    const int m0 = blockIdx.y * BM;
    const int n0 = blockIdx.x * BN;

    // n-tile lies entirely within one half (n0 multiple of 64)
    const float* Wsrc = (n0 < 256) ? (W1 + n0) : (W1 + 256 * 256 + (n0 - 256));

    const int ty = tid >> 4;          // 0..15 (m group)
    const int tx = tid & 15;          // 0..15 (n group)

    const int lrow = tid >> 2;        // 0..63  F row within tile
    const int lcol = (tid & 3) * 4;   // 0,4,8,12 (k within tile)
    const int wrow = tid >> 4;        // 0..15  k within tile
    const int wcol = (tid & 15) * 4;  // n within tile

    // c2[i][j] holds (C[i][2j], C[i][2j+1]) as packed f32x2
    unsigned long long c2[4][2] = {};

    for (int k0 = 0; k0 < 256; k0 += BK) {
        float4 fv = *(const float4*)(F + (size_t)(m0 + lrow) * 256 + k0 + lcol);
        Fs[lcol + 0][lrow] = fv.x;
        Fs[lcol + 1][lrow] = fv.y;
        Fs[lcol + 2][lrow] = fv.z;
        Fs[lcol + 3][lrow] = fv.w;

        *(float4*)&Ws[wrow][wcol] =
            *(const float4*)(Wsrc + (size_t)(k0 + wrow) * 256 + wcol);

        __syncthreads();

#pragma unroll
        for (int kk = 0; kk < BK; kk++) {
            float4 a = *(const float4*)&Fs[kk][ty * 4];
            // b pair-packed: float4 is 16B aligned -> reinterpret as 2x b64
            const unsigned long long* bp =
                (const unsigned long long*)&Ws[kk][tx * 4];
            unsigned long long b01 = bp[0];
            unsigned long long b23 = bp[1];

            unsigned long long a0 = pack_dup(a.x);
            unsigned long long a1 = pack_dup(a.y);
            unsigned long long a2 = pack_dup(a.z);
            unsigned long long a3 = pack_dup(a.w);

            ffma2(c2[0][0], a0, b01); ffma2(c2[0][1], a0, b23);
            ffma2(c2[1][0], a1, b01); ffma2(c2[1][1], a1, b23);
            ffma2(c2[2][0], a2, b01); ffma2(c2[2][1], a2, b23);
            ffma2(c2[3][0], a3, b01); ffma2(c2[3][1], a3, b23);
        }
        __syncthreads();
    }

#pragma unroll
    for (int i = 0; i < 4; i++) {
        float2 lo = unpack2(c2[i][0]);
        float2 hi = unpack2(c2[i][1]);
        float4 v = make_float4(lo.x, lo.y, hi.x, hi.y);
        *(float4*)(AB + (size_t)(m0 + ty * 4 + i) * 512 + n0 + tx * 4) = v;
    }
}

// ---------------------------------------------------------------------------
// Phase 2: per-(b,e) edge MLP tail + scatter.
// One warp per (b,e), 4 pairs per warp sequentially. b1/W2 frags in registers.
// Edge dtype (int32 vs int64) detected per-warp via ballot over the first 32
// odd 32-bit words: indices are < 512, so an int64 buffer has ALL of them
// zero; an int32 buffer has random indices there (P[all zero] ~ 512^-32).
// ---------------------------------------------------------------------------
__global__ __launch_bounds__(256) void edge_kernel(
    const float* __restrict__ AB,
    const float* __restrict__ b1,
    const float* __restrict__ W2,
    const float* __restrict__ b2,
    const void* __restrict__ edge_raw,
    float* __restrict__ out)
{
    const int tid  = threadIdx.x;
    const int warp = tid >> 5;
    const int lane = tid & 31;
    const int base = lane * 4;

    const int*       e32 = (const int*)edge_raw;
    const long long* e64 = (const long long*)edge_raw;

    // In-warp dtype detection (one broadcast load, no extra kernel)
    {
        int v = e32[2 * lane + 1];
        unsigned any = __ballot_sync(0xffffffffu, v != 0);
        // is64 == true when all odd words are zero
        const bool is64 = (any == 0u);

        const float4 b1a = *(const float4*)(b1 + base);
        const float4 b1b = *(const float4*)(b1 + base + 128);
        const float4 w2a = *(const float4*)(W2 + base);
        const float4 w2b = *(const float4*)(W2 + base + 128);
        const float  b2v = b2[0];

        const int wslot = blockIdx.x * 8 + warp;  // 0..32767

#pragma unroll
        for (int r = 0; r < 4; r++) {
            const int g = wslot * 4 + r;            // 0..131071  (b,e) pair
            const int b = g >> 14;                  // E = 16384
            const int e = g & (Ee - 1);

            int src, dst;
            if (is64) {
                src = (int)e64[e];
                dst = (int)e64[Ee + e];
            } else {
                src = e32[e];
                dst = e32[Ee + e];
            }

            const float* ar = AB + (((size_t)b * Nn + src) << 9);
            const float* br = AB + (((size_t)b * Nn + dst) << 9) + 256;

            float4 a0 = *(const float4*)(ar + base);
            float4 a1 = *(const float4*)(ar + base + 128);
            float4 c0 = *(const float4*)(br + base);
            float4 c1 = *(const float4*)(br + base + 128);

            float acc;
            acc  = fmaxf(a0.x + c0.x + b1a.x, 0.f) * w2a.x;
            acc += fmaxf(a0.y + c0.y + b1a.y, 0.f) * w2a.y;
            acc += fmaxf(a0.z + c0.z + b1a.z, 0.f) * w2a.z;
            acc += fmaxf(a0.w + c0.w + b1a.w, 0.f) * w2a.w;
            acc += fmaxf(a1.x + c1.x + b1b.x, 0.f) * w2b.x;
            acc += fmaxf(a1.y + c1.y + b1b.y, 0.f) * w2b.y;
            acc += fmaxf(a1.z + c1.z + b1b.z, 0.f) * w2b.z;
            acc += fmaxf(a1.w + c1.w + b1b.w, 0.f) * w2b.w;

            acc += __shfl_xor_sync(0xffffffffu, acc, 16);
            acc += __shfl_xor_sync(0xffffffffu, acc, 8);
            acc += __shfl_xor_sync(0xffffffffu, acc, 4);
            acc += __shfl_xor_sync(0xffffffffu, acc, 2);
            acc += __shfl_xor_sync(0xffffffffu, acc, 1);

            if (lane == 0) {
                const float z = acc + b2v;
                const float s = 1.0f / (1.0f + expf(-z));
                out[((size_t)b << 18) + ((size_t)src << 9) + (size_t)dst] = s;
            }
        }
    }
}

// ---------------------------------------------------------------------------
extern "C" void kernel_launch(void* const* d_in, const int* in_sizes, int n_in,
                              void* d_out, int out_size)
{
    const float* features = (const float*)d_in[0];   // (8,512,256)
    const float* W1       = (const float*)d_in[1];   // (512,256)
    const float* b1       = (const float*)d_in[2];   // (256)
    const float* W2       = (const float*)d_in[3];   // (256,1)
    const float* b2       = (const float*)d_in[4];   // (1)
    const void*  edge     = d_in[5];                 // (2,16384) int32 or int64
    float*       out      = (float*)d_out;           // (8,512,512)

    float* AB;
    cudaGetSymbolAddress((void**)&AB, g_AB);

    // Zero output (scatter only writes edge slots)
    cudaMemsetAsync(d_out, 0, (size_t)out_size * sizeof(float));

    // Phase 1: AB = F @ Wc
    dim3 ggrid(512 / BN, (Bsz * Nn) / BM);  // (8, 64)
    gemm_kernel<<<ggrid, 256>>>(features, W1, AB);

    // Phase 2: edge MLP tail + scatter. 131072 (b,e) / (8 warps * 4) = 4096 blocks
    edge_kernel<<<4096, 256>>>(AB, b1, W2, b2, edge, out);
}

// round 5
// speedup vs baseline: 1.7138x; 1.6650x over previous
#include <cuda_runtime.h>
#include <cstdint>

// Problem constants (fixed by the dataset)
#define Bsz 8
#define Nn  512
#define Dd  256
#define Ee  16384

// Scratch: AB[b*N + n][0:256] = F@W1_top, [256:512] = F@W1_bot  (8 MB)
__device__ float g_AB[(size_t)Bsz * Nn * 512];

// ---------------------------------------------------------------------------
// tf32 helpers (mma.sync is baseline PTX — compiles for sm_103 without 'a')
// ---------------------------------------------------------------------------
__device__ __forceinline__ uint32_t f2tf32(float x) {
    uint32_t r;
    asm("cvt.rna.tf32.f32 %0, %1;" : "=r"(r) : "f"(x));
    return r;
}

__device__ __forceinline__ void mma_tf32(
    float c[4], uint32_t a0, uint32_t a1, uint32_t a2, uint32_t a3,
    uint32_t b0, uint32_t b1)
{
    asm volatile(
        "mma.sync.aligned.m16n8k8.row.col.f32.tf32.tf32.f32 "
        "{%0,%1,%2,%3}, {%4,%5,%6,%7}, {%8,%9}, {%0,%1,%2,%3};"
        : "+f"(c[0]), "+f"(c[1]), "+f"(c[2]), "+f"(c[3])
        : "r"(a0), "r"(a1), "r"(a2), "r"(a3), "r"(b0), "r"(b1));
}

// ---------------------------------------------------------------------------
// Phase 1: tensor GEMM  AB(4096 x 512) = F(4096 x 256) @ Wc(256 x 512)
//   Wc[k][j] = W1[k*256 + j]             (j < 256)
//            = W1[(256+k)*256 + (j-256)] (j >= 256)
// CTA tile M=128 x N=64, K chunked by 32 through smem. 8 warps, 32x32 each.
// ---------------------------------------------------------------------------
#define A_STRIDE 36   /* 32 + 4 pad: conflict-free fragment LDS */
#define B_STRIDE 72   /* 64 + 8 pad */

__global__ __launch_bounds__(256) void gemm_tc_kernel(
    const float* __restrict__ F, const float* __restrict__ W1,
    float* __restrict__ AB)
{
    __shared__ uint32_t As[128 * A_STRIDE];   // 18432 B
    __shared__ uint32_t Bs[32 * B_STRIDE];    //  9216 B

    const int tid  = threadIdx.x;
    const int wid  = tid >> 5;
    const int lane = tid & 31;
    const int lq   = lane >> 2;   // 0..7
    const int lr   = lane & 3;    // 0..3

    const int n0 = blockIdx.x * 64;    // 0..448
    const int m0 = blockIdx.y * 128;   // 0..3968

    const int wm = wid >> 1;          // 0..3  (m quadrant, 32 rows)
    const int wn = wid & 1;           // 0..1  (n half, 32 cols)

    const float* Wsrc = (n0 < 256) ? (W1 + n0) : (W1 + 256 * 256 + (n0 - 256));

    float c[2][4][4] = {};            // [m-tile][n-tile][frag]

    for (int kc = 0; kc < 256; kc += 32) {
        // ---- Load A chunk: 128 rows x 32 k, coalesced float4, cvt to tf32
#pragma unroll
        for (int it = 0; it < 4; it++) {
            const int idx = it * 256 + tid;       // [0,1024)
            const int row = idx >> 3;
            const int k4  = idx & 7;
            float4 v = *(const float4*)(F + (size_t)(m0 + row) * 256 + kc + k4 * 4);
            uint32_t* d = &As[row * A_STRIDE + k4 * 4];
            d[0] = f2tf32(v.x); d[1] = f2tf32(v.y);
            d[2] = f2tf32(v.z); d[3] = f2tf32(v.w);
        }
        // ---- Load B chunk: 32 k x 64 n
#pragma unroll
        for (int it = 0; it < 2; it++) {
            const int idx = it * 256 + tid;       // [0,512)
            const int k   = idx >> 4;
            const int n4  = idx & 15;
            float4 v = *(const float4*)(Wsrc + (size_t)(kc + k) * 256 + n4 * 4);
            uint32_t* d = &Bs[k * B_STRIDE + n4 * 4];
            d[0] = f2tf32(v.x); d[1] = f2tf32(v.y);
            d[2] = f2tf32(v.z); d[3] = f2tf32(v.w);
        }
        __syncthreads();

        // ---- Compute: 4 k-steps of 8
#pragma unroll
        for (int k0 = 0; k0 < 32; k0 += 8) {
            uint32_t a[2][4];
#pragma unroll
            for (int i = 0; i < 2; i++) {
                const int rb = (wm * 32 + i * 16 + lq) * A_STRIDE + k0 + lr;
                a[i][0] = As[rb];
                a[i][1] = As[rb + 8 * A_STRIDE];
                a[i][2] = As[rb + 4];
                a[i][3] = As[rb + 8 * A_STRIDE + 4];
            }
            uint32_t b[4][2];
#pragma unroll
            for (int j = 0; j < 4; j++) {
                const int cb = (k0 + lr) * B_STRIDE + wn * 32 + j * 8 + lq;
                b[j][0] = Bs[cb];
                b[j][1] = Bs[cb + 4 * B_STRIDE];
            }
#pragma unroll
            for (int i = 0; i < 2; i++)
#pragma unroll
                for (int j = 0; j < 4; j++)
                    mma_tf32(c[i][j], a[i][0], a[i][1], a[i][2], a[i][3],
                             b[j][0], b[j][1]);
        }
        __syncthreads();
    }

    // ---- Epilogue: c{0,1}: row lq, cols 2*lr,2*lr+1 ; c{2,3}: row lq+8
#pragma unroll
    for (int i = 0; i < 2; i++) {
        const int rbase = m0 + wm * 32 + i * 16 + lq;
#pragma unroll
        for (int j = 0; j < 4; j++) {
            const int col = n0 + wn * 32 + j * 8 + 2 * lr;
            float* p0 = AB + (size_t)rbase * 512 + col;
            float* p1 = AB + (size_t)(rbase + 8) * 512 + col;
            *(float2*)p0 = make_float2(c[i][j][0], c[i][j][1]);
            *(float2*)p1 = make_float2(c[i][j][2], c[i][j][3]);
        }
    }
}

// ---------------------------------------------------------------------------
// Phase 2: per-(b,e) edge MLP tail + scatter (unchanged, passing).
// ---------------------------------------------------------------------------
__global__ __launch_bounds__(256) void edge_kernel(
    const float* __restrict__ AB,
    const float* __restrict__ b1,
    const float* __restrict__ W2,
    const float* __restrict__ b2,
    const void* __restrict__ edge_raw,
    float* __restrict__ out)
{
    const int tid  = threadIdx.x;
    const int warp = tid >> 5;
    const int lane = tid & 31;
    const int base = lane * 4;

    const int*       e32 = (const int*)edge_raw;
    const long long* e64 = (const long long*)edge_raw;

    // In-warp dtype detection: int64 buffer has all odd words zero.
    int v = e32[2 * lane + 1];
    unsigned any = __ballot_sync(0xffffffffu, v != 0);
    const bool is64 = (any == 0u);

    const float4 b1a = *(const float4*)(b1 + base);
    const float4 b1b = *(const float4*)(b1 + base + 128);
    const float4 w2a = *(const float4*)(W2 + base);
    const float4 w2b = *(const float4*)(W2 + base + 128);
    const float  b2v = b2[0];

    const int wslot = blockIdx.x * 8 + warp;  // 0..32767

#pragma unroll
    for (int r = 0; r < 4; r++) {
        const int g = wslot * 4 + r;            // 0..131071  (b,e) pair
        const int b = g >> 14;                  // E = 16384
        const int e = g & (Ee - 1);

        int src, dst;
        if (is64) {
            src = (int)e64[e];
            dst = (int)e64[Ee + e];
        } else {
            src = e32[e];
            dst = e32[Ee + e];
        }

        const float* ar = AB + (((size_t)b * Nn + src) << 9);
        const float* br = AB + (((size_t)b * Nn + dst) << 9) + 256;

        float4 a0 = *(const float4*)(ar + base);
        float4 a1 = *(const float4*)(ar + base + 128);
        float4 c0 = *(const float4*)(br + base);
        float4 c1 = *(const float4*)(br + base + 128);

        float acc;
        acc  = fmaxf(a0.x + c0.x + b1a.x, 0.f) * w2a.x;
        acc += fmaxf(a0.y + c0.y + b1a.y, 0.f) * w2a.y;
        acc += fmaxf(a0.z + c0.z + b1a.z, 0.f) * w2a.z;
        acc += fmaxf(a0.w + c0.w + b1a.w, 0.f) * w2a.w;
        acc += fmaxf(a1.x + c1.x + b1b.x, 0.f) * w2b.x;
        acc += fmaxf(a1.y + c1.y + b1b.y, 0.f) * w2b.y;
        acc += fmaxf(a1.z + c1.z + b1b.z, 0.f) * w2b.z;
        acc += fmaxf(a1.w + c1.w + b1b.w, 0.f) * w2b.w;

        acc += __shfl_xor_sync(0xffffffffu, acc, 16);
        acc += __shfl_xor_sync(0xffffffffu, acc, 8);
        acc += __shfl_xor_sync(0xffffffffu, acc, 4);
        acc += __shfl_xor_sync(0xffffffffu, acc, 2);
        acc += __shfl_xor_sync(0xffffffffu, acc, 1);

        if (lane == 0) {
            const float z = acc + b2v;
            const float s = 1.0f / (1.0f + expf(-z));
            out[((size_t)b << 18) + ((size_t)src << 9) + (size_t)dst] = s;
        }
    }
}

// ---------------------------------------------------------------------------
extern "C" void kernel_launch(void* const* d_in, const int* in_sizes, int n_in,
                              void* d_out, int out_size)
{
    const float* features = (const float*)d_in[0];   // (8,512,256)
    const float* W1       = (const float*)d_in[1];   // (512,256)
    const float* b1       = (const float*)d_in[2];   // (256)
    const float* W2       = (const float*)d_in[3];   // (256,1)
    const float* b2       = (const float*)d_in[4];   // (1)
    const void*  edge     = d_in[5];                 // (2,16384) int32 or int64
    float*       out      = (float*)d_out;           // (8,512,512)

    float* AB;
    cudaGetSymbolAddress((void**)&AB, g_AB);

    // Zero output (scatter only writes edge slots)
    cudaMemsetAsync(d_out, 0, (size_t)out_size * sizeof(float));

    // Phase 1: AB = F @ Wc  (mma.sync tf32)
    dim3 ggrid(8, 32);   // N-tiles x M-tiles
    gemm_tc_kernel<<<ggrid, 256>>>(features, W1, AB);

    // Phase 2: edge MLP tail + scatter
    edge_kernel<<<4096, 256>>>(AB, b1, W2, b2, edge, out);
}